// round 13
// baseline (speedup 1.0000x reference)
#include <cuda_runtime.h>
#include <cuda_fp16.h>
#include <math.h>
#include <stdint.h>

// ---------------- problem constants ----------------
namespace {
constexpr int B = 4, H = 64, W = 64, C = 768;
constexpr int HEADS = 12, HD = 64, WS = 14, HID = 3072;
constexpr int NWIN = 5;               // 70/14
constexpr int NWB  = NWIN * NWIN;     // 25 windows per batch
constexpr int NW   = B * NWB;         // 100 windows
constexpr int L    = WS * WS;         // 196 tokens per window
constexpr int NT   = NW * L;          // 19600 window tokens
constexpr int NP   = B * H * W;       // 16384 real pixels
constexpr int C3   = 3 * C;           // 2304
constexpr int RELN = 2 * WS - 1;      // 27
constexpr float EPS   = 1e-6f;
constexpr float SCALE = 0.125f;       // HD^-0.5
constexpr int PERSIST = 296;          // 2 CTAs/SM x 148 SMs
}

// ---------------- scratch (device globals; no allocation allowed) --------
__device__ __half g_ywin_h[(size_t)NT * C];    // LN1 out (window layout, fp16)
__device__ __half g_qkv_h[(size_t)NT * C3];    // qkv (fp16)
__device__ __half g_owin_h[(size_t)NT * C];    // attention out (fp16)
__device__ float  g_x1   [(size_t)NP * C];     // shortcut + proj(o)
__device__ __half g_h2_h [(size_t)NP * C];     // LN2 out (fp16)
__device__ __half g_m1_h [(size_t)NP * HID];   // gelu(fc1) (fp16)
// fp16 TRANSPOSED weights [N, K]
__device__ __half g_qkvw_t[(size_t)C3 * C];
__device__ __half g_projw_t[(size_t)C * C];
__device__ __half g_fc1w_t[(size_t)HID * C];
__device__ __half g_fc2w_t[(size_t)C * HID];

// window-row -> pixel-row index (-1 if padded)
__device__ __forceinline__ int winrow_to_pixel(int t) {
    int nw = t / L, l = t - nw * L;
    int b  = nw / NWB, r = nw - b * NWB;
    int wi = r / NWIN, wj = r - wi * NWIN;
    int i  = l / WS,   j  = l - i * WS;
    int hh = wi * WS + i, ww = wj * WS + j;
    if (hh >= H || ww >= W) return -1;
    return (b * H + hh) * W + ww;
}

__device__ __forceinline__ void mma_f16(float c[4], const uint32_t a[4],
                                        const uint32_t b0, const uint32_t b1) {
    asm volatile(
        "mma.sync.aligned.m16n8k16.row.col.f32.f16.f16.f32 "
        "{%0,%1,%2,%3}, {%4,%5,%6,%7}, {%8,%9}, {%0,%1,%2,%3};"
        : "+f"(c[0]), "+f"(c[1]), "+f"(c[2]), "+f"(c[3])
        : "r"(a[0]), "r"(a[1]), "r"(a[2]), "r"(a[3]), "r"(b0), "r"(b1));
}

__device__ __forceinline__ uint32_t smem_u32(const void* p) {
    uint32_t a;
    asm("{ .reg .u64 t; cvta.to.shared.u64 t, %1; cvt.u32.u64 %0, t; }"
        : "=r"(a) : "l"(p));
    return a;
}

// ---------------- weight transpose fp32 [K,N] -> fp16 [N,K] ----------------
__global__ void wt_kernel(const float* __restrict__ w, __half* __restrict__ wt,
                          int K, int N) {
    __shared__ float s[32][33];
    int n0 = blockIdx.x * 32, k0 = blockIdx.y * 32;
    int tx = threadIdx.x, ty = threadIdx.y;   // 32 x 8
#pragma unroll
    for (int i = 0; i < 32; i += 8)
        s[ty + i][tx] = w[(size_t)(k0 + ty + i) * N + n0 + tx];
    __syncthreads();
#pragma unroll
    for (int i = 0; i < 32; i += 8)
        wt[(size_t)(n0 + ty + i) * K + k0 + tx] = __float2half(s[tx][ty + i]);
}

// ---------------- LN1 + window gather (fp16 out, zero-fill padding) -------
__global__ void ln1_gather_kernel(const float* __restrict__ x,
                                  const float* __restrict__ sc,
                                  const float* __restrict__ bi) {
    int t = blockIdx.x;
    int tid = threadIdx.x;
    __half* y = g_ywin_h + (size_t)t * C;
    int pix = winrow_to_pixel(t);
    if (pix < 0) {
        for (int c = tid; c < C; c += blockDim.x) y[c] = __float2half(0.f);
        return;
    }
    const float* xr = x + (size_t)pix * C;
    float s = 0.f, s2 = 0.f;
    for (int c = tid; c < C; c += blockDim.x) { float v = xr[c]; s += v; s2 += v * v; }
    __shared__ float red[64];
    for (int o = 16; o; o >>= 1) {
        s  += __shfl_xor_sync(0xffffffffu, s, o);
        s2 += __shfl_xor_sync(0xffffffffu, s2, o);
    }
    int warp = tid >> 5, lane = tid & 31;
    if (!lane) { red[warp] = s; red[32 + warp] = s2; }
    __syncthreads();
    if (tid < 32) {
        float a  = (tid < 8) ? red[tid]      : 0.f;
        float b2 = (tid < 8) ? red[32 + tid] : 0.f;
        for (int o = 4; o; o >>= 1) {
            a  += __shfl_xor_sync(0xffffffffu, a, o);
            b2 += __shfl_xor_sync(0xffffffffu, b2, o);
        }
        if (!tid) { red[0] = a; red[1] = b2; }
    }
    __syncthreads();
    float mu  = red[0] / (float)C;
    float var = red[1] / (float)C - mu * mu;
    float inv = rsqrtf(var + EPS);
    for (int c = tid; c < C; c += blockDim.x)
        y[c] = __float2half((xr[c] - mu) * inv * sc[c] + bi[c]);
}

// ---------------- LN over contiguous rows (x1 -> h2 fp16) -----------------
__global__ void ln_rows_kernel(const float* __restrict__ in,
                               const float* __restrict__ sc,
                               const float* __restrict__ bi) {
    int t = blockIdx.x;
    int tid = threadIdx.x;
    const float* xr = in + (size_t)t * C;
    __half* y = g_h2_h + (size_t)t * C;
    float s = 0.f, s2 = 0.f;
    for (int c = tid; c < C; c += blockDim.x) { float v = xr[c]; s += v; s2 += v * v; }
    __shared__ float red[64];
    for (int o = 16; o; o >>= 1) {
        s  += __shfl_xor_sync(0xffffffffu, s, o);
        s2 += __shfl_xor_sync(0xffffffffu, s2, o);
    }
    int warp = tid >> 5, lane = tid & 31;
    if (!lane) { red[warp] = s; red[32 + warp] = s2; }
    __syncthreads();
    if (tid < 32) {
        float a  = (tid < 8) ? red[tid]      : 0.f;
        float b2 = (tid < 8) ? red[32 + tid] : 0.f;
        for (int o = 4; o; o >>= 1) {
            a  += __shfl_xor_sync(0xffffffffu, a, o);
            b2 += __shfl_xor_sync(0xffffffffu, b2, o);
        }
        if (!tid) { red[0] = a; red[1] = b2; }
    }
    __syncthreads();
    float mu  = red[0] / (float)C;
    float var = red[1] / (float)C - mu * mu;
    float inv = rsqrtf(var + EPS);
    for (int c = tid; c < C; c += blockDim.x)
        y[c] = __float2half((xr[c] - mu) * inv * sc[c] + bi[c]);
}

// ---------------- fp16 tensor-core GEMM v6: persistent tiles ---------------
// cp.async 4-stage ring, BK=32, 128x128 tile, 8 warps (4m x 2n), 32x64 warp.
// Persistent: grid = min(tiles, 296); each CTA loops over tiles, removing
// wave quantization.
constexpr int HG_RS = 40;                       // halfs per smem row
constexpr int HG_STG = 128 * HG_RS;             // halfs per stage per array
constexpr int HG_SMEM = 4 * HG_STG * 2 * 2;     // bytes (A+B, 4 stages)

template <int MODE>
__global__ void __launch_bounds__(256, 2)
hgemm_kernel(const __half* __restrict__ A,
             const __half* __restrict__ Bt,
             const float* __restrict__ bias,
             const float* __restrict__ aux,
             void* __restrict__ CoutV,
             int M, int N, int K) {
    extern __shared__ __half hsm[];
    __half* Asm = hsm;                 // 4 stages x HG_STG
    __half* Bsm = hsm + 4 * HG_STG;
    float*  Cf = (float*)CoutV;
    __half* Ch = (__half*)CoutV;

    int tid  = threadIdx.x;
    int warp = tid >> 5, lane = tid & 31;
    int wm = warp >> 1, wn = warp & 1;     // 4 x 2 warp grid
    int r = lane >> 2, cq = lane & 3;

    int srow = tid >> 1, part = tid & 1;
    uint32_t soff = (uint32_t)(srow * HG_RS + part * 16) * 2;   // bytes
    uint32_t abase = smem_u32(Asm) + soff;
    uint32_t bbase = smem_u32(Bsm) + soff;

    int ntm = (M + 127) >> 7, ntn = N >> 7;
    int ntiles = ntm * ntn;
    int nk = K >> 5;   // BK=32

    for (int tile = blockIdx.x; tile < ntiles; tile += gridDim.x) {
        int tm = tile / ntn, tn = tile - tm * ntn;
        int row0 = tm * 128, col0 = tn * 128;

        bool aok = (row0 + srow) < M;
        const __half* Ag = A + (size_t)(row0 + srow) * K + part * 16;
        const __half* Bg = Bt + (size_t)(col0 + srow) * K + part * 16;
        uint32_t asz = aok ? 16u : 0u;

        auto issue = [&](int t) {
            int s = t & 3;
            uint32_t ad = abase + (uint32_t)s * HG_STG * 2;
            uint32_t bd = bbase + (uint32_t)s * HG_STG * 2;
            const __half* Ap = Ag + (size_t)t * 32;
            const __half* Bp = Bg + (size_t)t * 32;
            asm volatile("cp.async.cg.shared.global [%0], [%1], 16, %2;"
                         :: "r"(ad), "l"(Ap), "r"(asz) : "memory");
            asm volatile("cp.async.cg.shared.global [%0], [%1], 16, %2;"
                         :: "r"(ad + 16), "l"(Ap + 8), "r"(asz) : "memory");
            asm volatile("cp.async.cg.shared.global [%0], [%1], 16;"
                         :: "r"(bd), "l"(Bp) : "memory");
            asm volatile("cp.async.cg.shared.global [%0], [%1], 16;"
                         :: "r"(bd + 16), "l"(Bp + 8) : "memory");
        };

        issue(0);
        asm volatile("cp.async.commit_group;" ::: "memory");
        issue(1);
        asm volatile("cp.async.commit_group;" ::: "memory");
        issue(2);
        asm volatile("cp.async.commit_group;" ::: "memory");

        float acc[2][8][4] = {};

        for (int t = 0; t < nk; t++) {
            asm volatile("cp.async.wait_group 2;" ::: "memory");
            __syncthreads();
            if (t + 3 < nk) issue(t + 3);
            asm volatile("cp.async.commit_group;" ::: "memory");

            const __half* Ab = Asm + (t & 3) * HG_STG;
            const __half* Bb = Bsm + (t & 3) * HG_STG;
#pragma unroll
            for (int ks = 0; ks < 2; ks++) {
                int k0 = ks * 16;
                uint32_t af[2][4];
#pragma unroll
                for (int mt = 0; mt < 2; mt++) {
                    int mb = wm * 32 + mt * 16 + r;
                    af[mt][0] = *(const uint32_t*)&Ab[mb * HG_RS + k0 + 2 * cq];
                    af[mt][1] = *(const uint32_t*)&Ab[(mb + 8) * HG_RS + k0 + 2 * cq];
                    af[mt][2] = *(const uint32_t*)&Ab[mb * HG_RS + k0 + 2 * cq + 8];
                    af[mt][3] = *(const uint32_t*)&Ab[(mb + 8) * HG_RS + k0 + 2 * cq + 8];
                }
#pragma unroll
                for (int nt = 0; nt < 8; nt++) {
                    int nb = wn * 64 + nt * 8 + r;
                    uint32_t b0 = *(const uint32_t*)&Bb[nb * HG_RS + k0 + 2 * cq];
                    uint32_t b1 = *(const uint32_t*)&Bb[nb * HG_RS + k0 + 2 * cq + 8];
#pragma unroll
                    for (int mt = 0; mt < 2; mt++)
                        mma_f16(acc[mt][nt], af[mt], b0, b1);
                }
            }
        }
        asm volatile("cp.async.wait_group 0;" ::: "memory");

        // epilogue
#pragma unroll
        for (int mt = 0; mt < 2; mt++) {
            int rA = row0 + wm * 32 + mt * 16 + r;
            int rB = rA + 8;
            bool okA = rA < M, okB = rB < M;
            int pixA = -1, pixB = -1;
            if (MODE == 1) {
                if (okA) pixA = winrow_to_pixel(rA);
                if (okB) pixB = winrow_to_pixel(rB);
            }
#pragma unroll
            for (int nt = 0; nt < 8; nt++) {
                int cb = col0 + wn * 64 + nt * 8 + cq * 2;
#pragma unroll
                for (int half = 0; half < 2; half++) {
                    int rr = half ? rB : rA;
                    bool ok = half ? okB : okA;
                    if (!ok) continue;
                    float v0 = acc[mt][nt][half * 2 + 0] + bias[cb];
                    float v1 = acc[mt][nt][half * 2 + 1] + bias[cb + 1];
                    if (MODE == 0) {
                        *(half2*)(Ch + (size_t)rr * N + cb) = __floats2half2_rn(v0, v1);
                    } else if (MODE == 1) {
                        int pix = half ? pixB : pixA;
                        if (pix >= 0) {
                            Cf[(size_t)pix * N + cb]     = aux[(size_t)pix * N + cb] + v0;
                            Cf[(size_t)pix * N + cb + 1] = aux[(size_t)pix * N + cb + 1] + v1;
                        }
                    } else if (MODE == 2) {
                        float g0 = 0.5f * v0 * (1.f + erff(v0 * 0.70710678118654752f));
                        float g1 = 0.5f * v1 * (1.f + erff(v1 * 0.70710678118654752f));
                        *(half2*)(Ch + (size_t)rr * N + cb) = __floats2half2_rn(g0, g1);
                    } else {
                        Cf[(size_t)rr * N + cb]     = aux[(size_t)rr * N + cb] + v0;
                        Cf[(size_t)rr * N + cb + 1] = aux[(size_t)rr * N + cb + 1] + v1;
                    }
                }
            }
        }
        __syncthreads();   // all reads of smem done before next tile's stores
    }
}

// ---------------- fused attention v3 (fp16 qkv) ----------------------------
constexpr int ATTN_SMEM_U32 =
    L * 33 + L * 32 + RELN * 66 + RELN * 66 + 8 * 132 + 8 * 400 + 8 * 64;
constexpr int ATTN_SMEM_BYTES = ATTN_SMEM_U32 * 4;

__global__ void attn_kernel(const float* __restrict__ rph,
                            const float* __restrict__ rpw) {
    extern __shared__ uint32_t smu[];
    half2* Ks2 = (half2*)smu;                  // [l*33 + d2]
    half2* Vs2 = Ks2 + L * 33;                 // [k*32 + lane]
    float* RH = (float*)(Vs2 + L * 32);
    float* RW = RH + RELN * 66;
    float* qb = RW + RELN * 66;
    float* pb = qb + 8 * 132;
    float* bb = pb + 8 * 400;

    int wh = blockIdx.x;
    int nw = wh / HEADS, head = wh - nw * HEADS;
    int tid = threadIdx.x;
    size_t base = (size_t)nw * L * C3 + head * HD;

    for (int idx = tid; idx < L * 32; idx += 256) {
        int l = idx >> 5, d2 = idx & 31;
        Ks2[l * 33 + d2] = *(const half2*)&g_qkv_h[base + (size_t)l * C3 + C + 2 * d2];
        Vs2[l * 32 + d2] = *(const half2*)&g_qkv_h[base + (size_t)l * C3 + 2 * C + 2 * d2];
    }
    for (int idx = tid; idx < RELN * HD; idx += 256) {
        int r = idx >> 6, d = idx & 63;
        RH[r * 66 + d] = rph[idx];
        RW[r * 66 + d] = rpw[idx];
    }
    __syncthreads();

    int warp = tid >> 5, lane = tid & 31;
    float* qv0 = qb + warp * 132;
    float* qv1 = qv0 + 66;
    float* prob0 = pb + warp * 400;
    float* prob1 = prob0 + 200;
    float* bw_ = bb + warp * 64;

    int koff[7];
    int kiL[7], kjL[7];
    bool ok[7];
#pragma unroll
    for (int s = 0; s < 7; s++) {
        int k = lane + 32 * s;
        ok[s] = (k < L);
        int kc = ok[s] ? k : (L - 1);
        kiL[s] = kc / WS;
        kjL[s] = kc - kiL[s] * WS;
        koff[s] = kc * 33;
    }

    for (int p = warp; p < L / 2; p += 8) {
        int q0 = 2 * p, q1 = q0 + 1;
        {
            float2 a = __half22float2(
                *(const half2*)&g_qkv_h[base + (size_t)q0 * C3 + lane * 2]);
            float2 b = __half22float2(
                *(const half2*)&g_qkv_h[base + (size_t)q1 * C3 + lane * 2]);
            *(float2*)&qv0[lane * 2] = a;
            *(float2*)&qv1[lane * 2] = b;
        }
        __syncwarp();

        int qi = q0 / WS, qj0 = q0 - qi * WS, qj1 = qj0 + 1;

        if (lane < 28) {
            int ksub = lane % 14;
            int qsel = lane / 14;
            const float* qp = qsel ? qv1 : qv0;
            const float* hp = RH + (qi - ksub + WS - 1) * 66;
            int qj = qsel ? qj1 : qj0;
            const float* wp = RW + (qj - ksub + WS - 1) * 66;
            float d1 = 0.f, d2a = 0.f;
#pragma unroll 8
            for (int d2 = 0; d2 < 32; d2++) {
                float2 q2 = *(const float2*)&qp[2 * d2];
                float2 h2 = *(const float2*)&hp[2 * d2];
                float2 w2 = *(const float2*)&wp[2 * d2];
                d1  = fmaf(q2.x, h2.x, d1);  d1  = fmaf(q2.y, h2.y, d1);
                d2a = fmaf(q2.x, w2.x, d2a); d2a = fmaf(q2.y, w2.y, d2a);
            }
            bw_[qsel * 14 + ksub] = d1;
            bw_[32 + qsel * 14 + ksub] = d2a;
        }
        __syncwarp();

        float sA[7] = {}, sB[7] = {};
#pragma unroll 8
        for (int d2 = 0; d2 < 32; d2++) {
            float2 qa2 = *(const float2*)&qv0[2 * d2];
            float2 qc2 = *(const float2*)&qv1[2 * d2];
#pragma unroll
            for (int s = 0; s < 7; s++) {
                float2 kf = __half22float2(Ks2[koff[s] + d2]);
                sA[s] = fmaf(qa2.x, kf.x, sA[s]);
                sA[s] = fmaf(qa2.y, kf.y, sA[s]);
                sB[s] = fmaf(qc2.x, kf.x, sB[s]);
                sB[s] = fmaf(qc2.y, kf.y, sB[s]);
            }
        }
        float ltA[7], ltB[7];
#pragma unroll
        for (int s = 0; s < 7; s++) {
            float bhA = bw_[kiL[s]],        bhB = bw_[14 + kiL[s]];
            float bwA = bw_[32 + kjL[s]],   bwB = bw_[46 + kjL[s]];
            ltA[s] = ok[s] ? (sA[s] * SCALE + bhA + bwA) : -1e30f;
            ltB[s] = ok[s] ? (sB[s] * SCALE + bhB + bwB) : -1e30f;
        }

        float mxA = ltA[0], mxB = ltB[0];
#pragma unroll
        for (int s = 1; s < 7; s++) { mxA = fmaxf(mxA, ltA[s]); mxB = fmaxf(mxB, ltB[s]); }
        for (int o = 16; o; o >>= 1) {
            mxA = fmaxf(mxA, __shfl_xor_sync(0xffffffffu, mxA, o));
            mxB = fmaxf(mxB, __shfl_xor_sync(0xffffffffu, mxB, o));
        }
        float smA = 0.f, smB = 0.f;
#pragma unroll
        for (int s = 0; s < 7; s++) {
            ltA[s] = expf(ltA[s] - mxA); smA += ltA[s];
            ltB[s] = expf(ltB[s] - mxB); smB += ltB[s];
        }
        for (int o = 16; o; o >>= 1) {
            smA += __shfl_xor_sync(0xffffffffu, smA, o);
            smB += __shfl_xor_sync(0xffffffffu, smB, o);
        }
        float ivA = 1.f / smA, ivB = 1.f / smB;
#pragma unroll
        for (int s = 0; s < 7; s++) {
            int k = lane + 32 * s;
            if (k < L) { prob0[k] = ltA[s] * ivA; prob1[k] = ltB[s] * ivB; }
        }
        __syncwarp();

        float a0 = 0.f, a1 = 0.f, b0 = 0.f, b1 = 0.f;
#pragma unroll 4
        for (int k = 0; k < L; k++) {
            float2 vf = __half22float2(Vs2[k * 32 + lane]);
            float pA = prob0[k], pB = prob1[k];
            a0 = fmaf(pA, vf.x, a0);
            a1 = fmaf(pA, vf.y, a1);
            b0 = fmaf(pB, vf.x, b0);
            b1 = fmaf(pB, vf.y, b1);
        }
        size_t orow = ((size_t)nw * L + q0) * C + head * HD + lane * 2;
        *(half2*)&g_owin_h[orow]     = __floats2half2_rn(a0, a1);
        *(half2*)&g_owin_h[orow + C] = __floats2half2_rn(b0, b1);
        __syncwarp();
    }
}

// ---------------- launch ---------------------------------------------------
static inline int pgrid(int tiles) { return tiles < PERSIST ? tiles : PERSIST; }

extern "C" void kernel_launch(void* const* d_in, const int* in_sizes, int n_in,
                              void* d_out, int out_size) {
    const float* x      = (const float*)d_in[0];
    const float* n1s    = (const float*)d_in[1];
    const float* n1b    = (const float*)d_in[2];
    const float* qkvw   = (const float*)d_in[3];
    const float* qkvb   = (const float*)d_in[4];
    const float* rph    = (const float*)d_in[5];
    const float* rpw    = (const float*)d_in[6];
    const float* projw  = (const float*)d_in[7];
    const float* projb  = (const float*)d_in[8];
    const float* n2s    = (const float*)d_in[9];
    const float* n2b    = (const float*)d_in[10];
    const float* fc1w   = (const float*)d_in[11];
    const float* fc1b   = (const float*)d_in[12];
    const float* fc2w   = (const float*)d_in[13];
    const float* fc2b   = (const float*)d_in[14];
    float* out = (float*)d_out;

    cudaFuncSetAttribute(attn_kernel, cudaFuncAttributeMaxDynamicSharedMemorySize,
                         ATTN_SMEM_BYTES);
    cudaFuncSetAttribute(hgemm_kernel<0>, cudaFuncAttributeMaxDynamicSharedMemorySize, HG_SMEM);
    cudaFuncSetAttribute(hgemm_kernel<1>, cudaFuncAttributeMaxDynamicSharedMemorySize, HG_SMEM);
    cudaFuncSetAttribute(hgemm_kernel<2>, cudaFuncAttributeMaxDynamicSharedMemorySize, HG_SMEM);
    cudaFuncSetAttribute(hgemm_kernel<3>, cudaFuncAttributeMaxDynamicSharedMemorySize, HG_SMEM);

    __half* ywin;  cudaGetSymbolAddress((void**)&ywin,  g_ywin_h);
    __half* qkv;   cudaGetSymbolAddress((void**)&qkv,   g_qkv_h);
    __half* owin;  cudaGetSymbolAddress((void**)&owin,  g_owin_h);
    float*  x1;    cudaGetSymbolAddress((void**)&x1,    g_x1);
    __half* h2;    cudaGetSymbolAddress((void**)&h2,    g_h2_h);
    __half* m1;    cudaGetSymbolAddress((void**)&m1,    g_m1_h);
    __half* qkvwt; cudaGetSymbolAddress((void**)&qkvwt, g_qkvw_t);
    __half* projwt;cudaGetSymbolAddress((void**)&projwt,g_projw_t);
    __half* fc1wt; cudaGetSymbolAddress((void**)&fc1wt, g_fc1w_t);
    __half* fc2wt; cudaGetSymbolAddress((void**)&fc2wt, g_fc2w_t);

    // 0) weights -> fp16 transposed [N,K]
    dim3 tb(32, 8);
    wt_kernel<<<dim3(C3 / 32, C / 32), tb>>>(qkvw, qkvwt, C, C3);
    wt_kernel<<<dim3(C / 32, C / 32), tb>>>(projw, projwt, C, C);
    wt_kernel<<<dim3(HID / 32, C / 32), tb>>>(fc1w, fc1wt, C, HID);
    wt_kernel<<<dim3(C / 32, HID / 32), tb>>>(fc2w, fc2wt, HID, C);

    // 1) LN1 + window partition (zero-pad), fp16 out
    ln1_gather_kernel<<<NT, 256>>>(x, n1s, n1b);

    int MT = (NT + 127) / 128;   // 154
    // 2) qkv = ywin @ qkv_w + qkv_b  (19600 x 2304 x 768), fp16 out
    hgemm_kernel<0><<<pgrid(MT * (C3 / 128)), 256, HG_SMEM>>>(
        ywin, qkvwt, qkvb, nullptr, qkv, NT, C3, C);

    // 3) fused windowed attention v3, fp16 out
    attn_kernel<<<NW * HEADS, 256, ATTN_SMEM_BYTES>>>(rph, rpw);

    // 4) x1 = shortcut + (owin @ proj_w + proj_b)  (scatter, crop padding)
    hgemm_kernel<1><<<pgrid(MT * (C / 128)), 256, HG_SMEM>>>(
        owin, projwt, projb, x, x1, NT, C, C);

    // 5) LN2 -> fp16
    ln_rows_kernel<<<NP, 256>>>(x1, n2s, n2b);

    // 6) m1 = gelu(h2 @ fc1_w + fc1_b)  (16384 x 3072 x 768), fp16 out
    hgemm_kernel<2><<<pgrid((NP / 128) * (HID / 128)), 256, HG_SMEM>>>(
        h2, fc1wt, fc1b, nullptr, m1, NP, HID, C);

    // 7) out = x1 + m1 @ fc2_w + fc2_b  (16384 x 768 x 3072), fp32 out
    hgemm_kernel<3><<<pgrid((NP / 128) * (C / 128)), 256, HG_SMEM>>>(
        m1, fc2wt, fc2b, x1, out, NP, C, HID);
}

// round 14
// speedup vs baseline: 1.1866x; 1.1866x over previous
#include <cuda_runtime.h>
#include <cuda_fp16.h>
#include <math.h>
#include <stdint.h>

// ---------------- problem constants ----------------
namespace {
constexpr int B = 4, H = 64, W = 64, C = 768;
constexpr int HEADS = 12, HD = 64, WS = 14, HID = 3072;
constexpr int NWIN = 5;               // 70/14
constexpr int NWB  = NWIN * NWIN;     // 25 windows per batch
constexpr int NW   = B * NWB;         // 100 windows
constexpr int L    = WS * WS;         // 196 tokens per window
constexpr int NT   = NW * L;          // 19600 window tokens
constexpr int NP   = B * H * W;       // 16384 real pixels
constexpr int C3   = 3 * C;           // 2304
constexpr int RELN = 2 * WS - 1;      // 27
constexpr float EPS   = 1e-6f;
constexpr float SCALE = 0.125f;       // HD^-0.5
}

// ---------------- scratch (device globals; no allocation allowed) --------
__device__ __half g_ywin_h[(size_t)NT * C];    // LN1 out (window layout, fp16)
__device__ __half g_qkv_h[(size_t)NT * C3];    // qkv (fp16)
__device__ __half g_owin_h[(size_t)NT * C];    // attention out (fp16)
__device__ float  g_x1   [(size_t)NP * C];     // shortcut + proj(o)
__device__ __half g_h2_h [(size_t)NP * C];     // LN2 out (fp16)
__device__ __half g_m1_h [(size_t)NP * HID];   // gelu(fc1) (fp16)
// fp16 TRANSPOSED weights [N, K]
__device__ __half g_qkvw_t[(size_t)C3 * C];
__device__ __half g_projw_t[(size_t)C * C];
__device__ __half g_fc1w_t[(size_t)HID * C];
__device__ __half g_fc2w_t[(size_t)C * HID];

// window-row -> pixel-row index (-1 if padded)
__device__ __forceinline__ int winrow_to_pixel(int t) {
    int nw = t / L, l = t - nw * L;
    int b  = nw / NWB, r = nw - b * NWB;
    int wi = r / NWIN, wj = r - wi * NWIN;
    int i  = l / WS,   j  = l - i * WS;
    int hh = wi * WS + i, ww = wj * WS + j;
    if (hh >= H || ww >= W) return -1;
    return (b * H + hh) * W + ww;
}

__device__ __forceinline__ void mma_f16(float c[4], const uint32_t a[4],
                                        const uint32_t b0, const uint32_t b1) {
    asm volatile(
        "mma.sync.aligned.m16n8k16.row.col.f32.f16.f16.f32 "
        "{%0,%1,%2,%3}, {%4,%5,%6,%7}, {%8,%9}, {%0,%1,%2,%3};"
        : "+f"(c[0]), "+f"(c[1]), "+f"(c[2]), "+f"(c[3])
        : "r"(a[0]), "r"(a[1]), "r"(a[2]), "r"(a[3]), "r"(b0), "r"(b1));
}

__device__ __forceinline__ uint32_t smem_u32(const void* p) {
    uint32_t a;
    asm("{ .reg .u64 t; cvta.to.shared.u64 t, %1; cvt.u32.u64 %0, t; }"
        : "=r"(a) : "l"(p));
    return a;
}

// fast exact-enough gelu: tanh form with HW tanh.approx (MUFU)
__device__ __forceinline__ float fast_gelu(float v) {
    float u = 0.7978845608028654f * (v + 0.044715f * v * v * v);
    float t;
    asm("tanh.approx.f32 %0, %1;" : "=f"(t) : "f"(u));
    return 0.5f * v * (1.f + t);
}

// ---------------- weight transpose fp32 [K,N] -> fp16 [N,K] ----------------
__global__ void wt_kernel(const float* __restrict__ w, __half* __restrict__ wt,
                          int K, int N) {
    __shared__ float s[32][33];
    int n0 = blockIdx.x * 32, k0 = blockIdx.y * 32;
    int tx = threadIdx.x, ty = threadIdx.y;   // 32 x 8
#pragma unroll
    for (int i = 0; i < 32; i += 8)
        s[ty + i][tx] = w[(size_t)(k0 + ty + i) * N + n0 + tx];
    __syncthreads();
#pragma unroll
    for (int i = 0; i < 32; i += 8)
        wt[(size_t)(n0 + ty + i) * K + k0 + tx] = __float2half(s[tx][ty + i]);
}

// ---------------- LN1 + window gather (fp16 out, zero-fill padding) -------
__global__ void ln1_gather_kernel(const float* __restrict__ x,
                                  const float* __restrict__ sc,
                                  const float* __restrict__ bi) {
    int t = blockIdx.x;
    int tid = threadIdx.x;
    __half* y = g_ywin_h + (size_t)t * C;
    int pix = winrow_to_pixel(t);
    if (pix < 0) {
        for (int c = tid; c < C; c += blockDim.x) y[c] = __float2half(0.f);
        return;
    }
    const float* xr = x + (size_t)pix * C;
    float s = 0.f, s2 = 0.f;
    for (int c = tid; c < C; c += blockDim.x) { float v = xr[c]; s += v; s2 += v * v; }
    __shared__ float red[64];
    for (int o = 16; o; o >>= 1) {
        s  += __shfl_xor_sync(0xffffffffu, s, o);
        s2 += __shfl_xor_sync(0xffffffffu, s2, o);
    }
    int warp = tid >> 5, lane = tid & 31;
    if (!lane) { red[warp] = s; red[32 + warp] = s2; }
    __syncthreads();
    if (tid < 32) {
        float a  = (tid < 8) ? red[tid]      : 0.f;
        float b2 = (tid < 8) ? red[32 + tid] : 0.f;
        for (int o = 4; o; o >>= 1) {
            a  += __shfl_xor_sync(0xffffffffu, a, o);
            b2 += __shfl_xor_sync(0xffffffffu, b2, o);
        }
        if (!tid) { red[0] = a; red[1] = b2; }
    }
    __syncthreads();
    float mu  = red[0] / (float)C;
    float var = red[1] / (float)C - mu * mu;
    float inv = rsqrtf(var + EPS);
    for (int c = tid; c < C; c += blockDim.x)
        y[c] = __float2half((xr[c] - mu) * inv * sc[c] + bi[c]);
}

// ---------------- LN over contiguous rows (x1 -> h2 fp16) -----------------
__global__ void ln_rows_kernel(const float* __restrict__ in,
                               const float* __restrict__ sc,
                               const float* __restrict__ bi) {
    int t = blockIdx.x;
    int tid = threadIdx.x;
    const float* xr = in + (size_t)t * C;
    __half* y = g_h2_h + (size_t)t * C;
    float s = 0.f, s2 = 0.f;
    for (int c = tid; c < C; c += blockDim.x) { float v = xr[c]; s += v; s2 += v * v; }
    __shared__ float red[64];
    for (int o = 16; o; o >>= 1) {
        s  += __shfl_xor_sync(0xffffffffu, s, o);
        s2 += __shfl_xor_sync(0xffffffffu, s2, o);
    }
    int warp = tid >> 5, lane = tid & 31;
    if (!lane) { red[warp] = s; red[32 + warp] = s2; }
    __syncthreads();
    if (tid < 32) {
        float a  = (tid < 8) ? red[tid]      : 0.f;
        float b2 = (tid < 8) ? red[32 + tid] : 0.f;
        for (int o = 4; o; o >>= 1) {
            a  += __shfl_xor_sync(0xffffffffu, a, o);
            b2 += __shfl_xor_sync(0xffffffffu, b2, o);
        }
        if (!tid) { red[0] = a; red[1] = b2; }
    }
    __syncthreads();
    float mu  = red[0] / (float)C;
    float var = red[1] / (float)C - mu * mu;
    float inv = rsqrtf(var + EPS);
    for (int c = tid; c < C; c += blockDim.x)
        y[c] = __float2half((xr[c] - mu) * inv * sc[c] + bi[c]);
}

// ---------------- fp16 tensor-core GEMM v7: cp.async, BK=64, 3 stages ------
// A [M,K] fp16 k-major; Bt [N,K] fp16 k-major (pre-transposed weights).
// 128x128 block tile, 8 warps (4m x 2n), warp tile 32x64, BK=64.
// 3-stage ring, always-commit group accounting (wait_group 1 is exact).
// Row stride 72 halfs -> fragment LDS words (4r+cq) bijective mod 32.
// Smem 110592B/CTA -> 2 CTAs/SM.
constexpr int HG_RS = 72;                       // halfs per smem row
constexpr int HG_STG = 128 * HG_RS;             // halfs per stage per array
constexpr int HG_SMEM = 3 * HG_STG * 2 * 2;     // bytes (A+B, 3 stages)

template <int MODE>
__global__ void __launch_bounds__(256, 2)
hgemm_kernel(const __half* __restrict__ A,
             const __half* __restrict__ Bt,
             const float* __restrict__ bias,
             const float* __restrict__ aux,
             void* __restrict__ CoutV,
             int M, int N, int K) {
    extern __shared__ __half hsm[];
    __half* Asm = hsm;                 // 3 stages x HG_STG
    __half* Bsm = hsm + 3 * HG_STG;
    float*  Cf = (float*)CoutV;
    __half* Ch = (__half*)CoutV;

    int tid  = threadIdx.x;
    int warp = tid >> 5, lane = tid & 31;
    int wm = warp >> 1, wn = warp & 1;     // 4 x 2 warp grid
    int row0 = blockIdx.y * 128, col0 = blockIdx.x * 128;
    int r = lane >> 2, cq = lane & 3;

    // staging: srow = tid>>3 (+32i), scp = tid&7 (16B chunk within 64-half row)
    int srow = tid >> 3, scp = tid & 7;
    const __half* AgI[4];
    const __half* BgI[4];
    uint32_t off[4];
    bool aok[4];
#pragma unroll
    for (int i = 0; i < 4; i++) {
        int row = srow + 32 * i;
        aok[i] = (row0 + row) < M;
        AgI[i] = A + (size_t)(row0 + row) * K + scp * 8;
        BgI[i] = Bt + (size_t)(col0 + row) * K + scp * 8;
        off[i] = (uint32_t)(row * HG_RS + scp * 8) * 2;
    }
    uint32_t abase = smem_u32(Asm);
    uint32_t bbase = smem_u32(Bsm);

    auto issue = [&](int t) {
        int s = t % 3;
        uint32_t ao = abase + (uint32_t)s * HG_STG * 2;
        uint32_t bo = bbase + (uint32_t)s * HG_STG * 2;
#pragma unroll
        for (int i = 0; i < 4; i++) {
            uint32_t asz = aok[i] ? 16u : 0u;
            asm volatile("cp.async.cg.shared.global [%0], [%1], 16, %2;"
                         :: "r"(ao + off[i]), "l"(AgI[i] + (size_t)t * 64),
                            "r"(asz) : "memory");
            asm volatile("cp.async.cg.shared.global [%0], [%1], 16;"
                         :: "r"(bo + off[i]), "l"(BgI[i] + (size_t)t * 64)
                         : "memory");
        }
    };

    int nk = K >> 6;   // BK=64
    issue(0);
    asm volatile("cp.async.commit_group;" ::: "memory");
    issue(1);
    asm volatile("cp.async.commit_group;" ::: "memory");

    float acc[2][8][4] = {};

    for (int t = 0; t < nk; t++) {
        asm volatile("cp.async.wait_group 1;" ::: "memory");
        __syncthreads();
        if (t + 2 < nk) issue(t + 2);
        asm volatile("cp.async.commit_group;" ::: "memory");   // always

        const __half* Ab = Asm + (t % 3) * HG_STG;
        const __half* Bb = Bsm + (t % 3) * HG_STG;
#pragma unroll
        for (int ks = 0; ks < 4; ks++) {
            int k0 = ks * 16;
            uint32_t af[2][4];
#pragma unroll
            for (int mt = 0; mt < 2; mt++) {
                int mb = wm * 32 + mt * 16 + r;
                af[mt][0] = *(const uint32_t*)&Ab[mb * HG_RS + k0 + 2 * cq];
                af[mt][1] = *(const uint32_t*)&Ab[(mb + 8) * HG_RS + k0 + 2 * cq];
                af[mt][2] = *(const uint32_t*)&Ab[mb * HG_RS + k0 + 2 * cq + 8];
                af[mt][3] = *(const uint32_t*)&Ab[(mb + 8) * HG_RS + k0 + 2 * cq + 8];
            }
#pragma unroll
            for (int nt = 0; nt < 8; nt++) {
                int nb = wn * 64 + nt * 8 + r;
                uint32_t b0 = *(const uint32_t*)&Bb[nb * HG_RS + k0 + 2 * cq];
                uint32_t b1 = *(const uint32_t*)&Bb[nb * HG_RS + k0 + 2 * cq + 8];
#pragma unroll
                for (int mt = 0; mt < 2; mt++)
                    mma_f16(acc[mt][nt], af[mt], b0, b1);
            }
        }
    }

    // epilogue: acc[mt][nt][{0,1}] -> row rA cols cb,cb+1 ; [{2,3}] -> rA+8
#pragma unroll
    for (int mt = 0; mt < 2; mt++) {
        int rA = row0 + wm * 32 + mt * 16 + r;
        int rB = rA + 8;
        bool okA = rA < M, okB = rB < M;
        int pixA = -1, pixB = -1;
        if (MODE == 1) {
            if (okA) pixA = winrow_to_pixel(rA);
            if (okB) pixB = winrow_to_pixel(rB);
        }
#pragma unroll
        for (int nt = 0; nt < 8; nt++) {
            int cb = col0 + wn * 64 + nt * 8 + cq * 2;
#pragma unroll
            for (int half = 0; half < 2; half++) {
                int rr = half ? rB : rA;
                bool ok = half ? okB : okA;
                if (!ok) continue;
                float v0 = acc[mt][nt][half * 2 + 0] + bias[cb];
                float v1 = acc[mt][nt][half * 2 + 1] + bias[cb + 1];
                if (MODE == 0) {
                    *(half2*)(Ch + (size_t)rr * N + cb) = __floats2half2_rn(v0, v1);
                } else if (MODE == 1) {
                    int pix = half ? pixB : pixA;
                    if (pix >= 0) {
                        Cf[(size_t)pix * N + cb]     = aux[(size_t)pix * N + cb] + v0;
                        Cf[(size_t)pix * N + cb + 1] = aux[(size_t)pix * N + cb + 1] + v1;
                    }
                } else if (MODE == 2) {
                    *(half2*)(Ch + (size_t)rr * N + cb) =
                        __floats2half2_rn(fast_gelu(v0), fast_gelu(v1));
                } else {
                    Cf[(size_t)rr * N + cb]     = aux[(size_t)rr * N + cb] + v0;
                    Cf[(size_t)rr * N + cb + 1] = aux[(size_t)rr * N + cb + 1] + v1;
                }
            }
        }
    }
}

// ---------------- fused attention v3 (fp16 qkv) ----------------------------
constexpr int ATTN_SMEM_U32 =
    L * 33 + L * 32 + RELN * 66 + RELN * 66 + 8 * 132 + 8 * 400 + 8 * 64;
constexpr int ATTN_SMEM_BYTES = ATTN_SMEM_U32 * 4;

__global__ void attn_kernel(const float* __restrict__ rph,
                            const float* __restrict__ rpw) {
    extern __shared__ uint32_t smu[];
    half2* Ks2 = (half2*)smu;                  // [l*33 + d2]
    half2* Vs2 = Ks2 + L * 33;                 // [k*32 + lane]
    float* RH = (float*)(Vs2 + L * 32);
    float* RW = RH + RELN * 66;
    float* qb = RW + RELN * 66;
    float* pb = qb + 8 * 132;
    float* bb = pb + 8 * 400;

    int wh = blockIdx.x;
    int nw = wh / HEADS, head = wh - nw * HEADS;
    int tid = threadIdx.x;
    size_t base = (size_t)nw * L * C3 + head * HD;

    for (int idx = tid; idx < L * 32; idx += 256) {
        int l = idx >> 5, d2 = idx & 31;
        Ks2[l * 33 + d2] = *(const half2*)&g_qkv_h[base + (size_t)l * C3 + C + 2 * d2];
        Vs2[l * 32 + d2] = *(const half2*)&g_qkv_h[base + (size_t)l * C3 + 2 * C + 2 * d2];
    }
    for (int idx = tid; idx < RELN * HD; idx += 256) {
        int r = idx >> 6, d = idx & 63;
        RH[r * 66 + d] = rph[idx];
        RW[r * 66 + d] = rpw[idx];
    }
    __syncthreads();

    int warp = tid >> 5, lane = tid & 31;
    float* qv0 = qb + warp * 132;
    float* qv1 = qv0 + 66;
    float* prob0 = pb + warp * 400;
    float* prob1 = prob0 + 200;
    float* bw_ = bb + warp * 64;

    int koff[7];
    int kiL[7], kjL[7];
    bool ok[7];
#pragma unroll
    for (int s = 0; s < 7; s++) {
        int k = lane + 32 * s;
        ok[s] = (k < L);
        int kc = ok[s] ? k : (L - 1);
        kiL[s] = kc / WS;
        kjL[s] = kc - kiL[s] * WS;
        koff[s] = kc * 33;
    }

    for (int p = warp; p < L / 2; p += 8) {
        int q0 = 2 * p, q1 = q0 + 1;
        {
            float2 a = __half22float2(
                *(const half2*)&g_qkv_h[base + (size_t)q0 * C3 + lane * 2]);
            float2 b = __half22float2(
                *(const half2*)&g_qkv_h[base + (size_t)q1 * C3 + lane * 2]);
            *(float2*)&qv0[lane * 2] = a;
            *(float2*)&qv1[lane * 2] = b;
        }
        __syncwarp();

        int qi = q0 / WS, qj0 = q0 - qi * WS, qj1 = qj0 + 1;

        if (lane < 28) {
            int ksub = lane % 14;
            int qsel = lane / 14;
            const float* qp = qsel ? qv1 : qv0;
            const float* hp = RH + (qi - ksub + WS - 1) * 66;
            int qj = qsel ? qj1 : qj0;
            const float* wp = RW + (qj - ksub + WS - 1) * 66;
            float d1 = 0.f, d2a = 0.f;
#pragma unroll 8
            for (int d2 = 0; d2 < 32; d2++) {
                float2 q2 = *(const float2*)&qp[2 * d2];
                float2 h2 = *(const float2*)&hp[2 * d2];
                float2 w2 = *(const float2*)&wp[2 * d2];
                d1  = fmaf(q2.x, h2.x, d1);  d1  = fmaf(q2.y, h2.y, d1);
                d2a = fmaf(q2.x, w2.x, d2a); d2a = fmaf(q2.y, w2.y, d2a);
            }
            bw_[qsel * 14 + ksub] = d1;
            bw_[32 + qsel * 14 + ksub] = d2a;
        }
        __syncwarp();

        float sA[7] = {}, sB[7] = {};
#pragma unroll 8
        for (int d2 = 0; d2 < 32; d2++) {
            float2 qa2 = *(const float2*)&qv0[2 * d2];
            float2 qc2 = *(const float2*)&qv1[2 * d2];
#pragma unroll
            for (int s = 0; s < 7; s++) {
                float2 kf = __half22float2(Ks2[koff[s] + d2]);
                sA[s] = fmaf(qa2.x, kf.x, sA[s]);
                sA[s] = fmaf(qa2.y, kf.y, sA[s]);
                sB[s] = fmaf(qc2.x, kf.x, sB[s]);
                sB[s] = fmaf(qc2.y, kf.y, sB[s]);
            }
        }
        float ltA[7], ltB[7];
#pragma unroll
        for (int s = 0; s < 7; s++) {
            float bhA = bw_[kiL[s]],        bhB = bw_[14 + kiL[s]];
            float bwA = bw_[32 + kjL[s]],   bwB = bw_[46 + kjL[s]];
            ltA[s] = ok[s] ? (sA[s] * SCALE + bhA + bwA) : -1e30f;
            ltB[s] = ok[s] ? (sB[s] * SCALE + bhB + bwB) : -1e30f;
        }

        float mxA = ltA[0], mxB = ltB[0];
#pragma unroll
        for (int s = 1; s < 7; s++) { mxA = fmaxf(mxA, ltA[s]); mxB = fmaxf(mxB, ltB[s]); }
        for (int o = 16; o; o >>= 1) {
            mxA = fmaxf(mxA, __shfl_xor_sync(0xffffffffu, mxA, o));
            mxB = fmaxf(mxB, __shfl_xor_sync(0xffffffffu, mxB, o));
        }
        float smA = 0.f, smB = 0.f;
#pragma unroll
        for (int s = 0; s < 7; s++) {
            ltA[s] = expf(ltA[s] - mxA); smA += ltA[s];
            ltB[s] = expf(ltB[s] - mxB); smB += ltB[s];
        }
        for (int o = 16; o; o >>= 1) {
            smA += __shfl_xor_sync(0xffffffffu, smA, o);
            smB += __shfl_xor_sync(0xffffffffu, smB, o);
        }
        float ivA = 1.f / smA, ivB = 1.f / smB;
#pragma unroll
        for (int s = 0; s < 7; s++) {
            int k = lane + 32 * s;
            if (k < L) { prob0[k] = ltA[s] * ivA; prob1[k] = ltB[s] * ivB; }
        }
        __syncwarp();

        float a0 = 0.f, a1 = 0.f, b0 = 0.f, b1 = 0.f;
#pragma unroll 4
        for (int k = 0; k < L; k++) {
            float2 vf = __half22float2(Vs2[k * 32 + lane]);
            float pA = prob0[k], pB = prob1[k];
            a0 = fmaf(pA, vf.x, a0);
            a1 = fmaf(pA, vf.y, a1);
            b0 = fmaf(pB, vf.x, b0);
            b1 = fmaf(pB, vf.y, b1);
        }
        size_t orow = ((size_t)nw * L + q0) * C + head * HD + lane * 2;
        *(half2*)&g_owin_h[orow]     = __floats2half2_rn(a0, a1);
        *(half2*)&g_owin_h[orow + C] = __floats2half2_rn(b0, b1);
        __syncwarp();
    }
}

// ---------------- launch ---------------------------------------------------
extern "C" void kernel_launch(void* const* d_in, const int* in_sizes, int n_in,
                              void* d_out, int out_size) {
    const float* x      = (const float*)d_in[0];
    const float* n1s    = (const float*)d_in[1];
    const float* n1b    = (const float*)d_in[2];
    const float* qkvw   = (const float*)d_in[3];
    const float* qkvb   = (const float*)d_in[4];
    const float* rph    = (const float*)d_in[5];
    const float* rpw    = (const float*)d_in[6];
    const float* projw  = (const float*)d_in[7];
    const float* projb  = (const float*)d_in[8];
    const float* n2s    = (const float*)d_in[9];
    const float* n2b    = (const float*)d_in[10];
    const float* fc1w   = (const float*)d_in[11];
    const float* fc1b   = (const float*)d_in[12];
    const float* fc2w   = (const float*)d_in[13];
    const float* fc2b   = (const float*)d_in[14];
    float* out = (float*)d_out;

    cudaFuncSetAttribute(attn_kernel, cudaFuncAttributeMaxDynamicSharedMemorySize,
                         ATTN_SMEM_BYTES);
    cudaFuncSetAttribute(hgemm_kernel<0>, cudaFuncAttributeMaxDynamicSharedMemorySize, HG_SMEM);
    cudaFuncSetAttribute(hgemm_kernel<1>, cudaFuncAttributeMaxDynamicSharedMemorySize, HG_SMEM);
    cudaFuncSetAttribute(hgemm_kernel<2>, cudaFuncAttributeMaxDynamicSharedMemorySize, HG_SMEM);
    cudaFuncSetAttribute(hgemm_kernel<3>, cudaFuncAttributeMaxDynamicSharedMemorySize, HG_SMEM);

    __half* ywin;  cudaGetSymbolAddress((void**)&ywin,  g_ywin_h);
    __half* qkv;   cudaGetSymbolAddress((void**)&qkv,   g_qkv_h);
    __half* owin;  cudaGetSymbolAddress((void**)&owin,  g_owin_h);
    float*  x1;    cudaGetSymbolAddress((void**)&x1,    g_x1);
    __half* h2;    cudaGetSymbolAddress((void**)&h2,    g_h2_h);
    __half* m1;    cudaGetSymbolAddress((void**)&m1,    g_m1_h);
    __half* qkvwt; cudaGetSymbolAddress((void**)&qkvwt, g_qkvw_t);
    __half* projwt;cudaGetSymbolAddress((void**)&projwt,g_projw_t);
    __half* fc1wt; cudaGetSymbolAddress((void**)&fc1wt, g_fc1w_t);
    __half* fc2wt; cudaGetSymbolAddress((void**)&fc2wt, g_fc2w_t);

    // 0) weights -> fp16 transposed [N,K]
    dim3 tb(32, 8);
    wt_kernel<<<dim3(C3 / 32, C / 32), tb>>>(qkvw, qkvwt, C, C3);
    wt_kernel<<<dim3(C / 32, C / 32), tb>>>(projw, projwt, C, C);
    wt_kernel<<<dim3(HID / 32, C / 32), tb>>>(fc1w, fc1wt, C, HID);
    wt_kernel<<<dim3(C / 32, HID / 32), tb>>>(fc2w, fc2wt, HID, C);

    // 1) LN1 + window partition (zero-pad), fp16 out
    ln1_gather_kernel<<<NT, 256>>>(x, n1s, n1b);

    // 2) qkv = ywin @ qkv_w + qkv_b           (19600 x 2304 x 768), fp16 out
    {
        dim3 grid(C3 / 128, (NT + 127) / 128);
        hgemm_kernel<0><<<grid, 256, HG_SMEM>>>(ywin, qkvwt, qkvb, nullptr, qkv, NT, C3, C);
    }

    // 3) fused windowed attention v3, fp16 out
    attn_kernel<<<NW * HEADS, 256, ATTN_SMEM_BYTES>>>(rph, rpw);

    // 4) x1 = shortcut + (owin @ proj_w + proj_b)  (scatter, crop padding)
    {
        dim3 grid(C / 128, (NT + 127) / 128);
        hgemm_kernel<1><<<grid, 256, HG_SMEM>>>(owin, projwt, projb, x, x1, NT, C, C);
    }

    // 5) LN2 -> fp16
    ln_rows_kernel<<<NP, 256>>>(x1, n2s, n2b);

    // 6) m1 = gelu(h2 @ fc1_w + fc1_b)        (16384 x 3072 x 768), fp16 out
    {
        dim3 grid(HID / 128, NP / 128);
        hgemm_kernel<2><<<grid, 256, HG_SMEM>>>(h2, fc1wt, fc1b, nullptr, m1, NP, HID, C);
    }

    // 7) out = x1 + m1 @ fc2_w + fc2_b        (16384 x 768 x 3072), fp32 out
    {
        dim3 grid(C / 128, NP / 128);
        hgemm_kernel<3><<<grid, 256, HG_SMEM>>>(m1, fc2wt, fc2b, x1, out, NP, C, HID);
    }
}

// round 15
// speedup vs baseline: 1.2366x; 1.0421x over previous
#include <cuda_runtime.h>
#include <cuda_fp16.h>
#include <math.h>
#include <stdint.h>

// ---------------- problem constants ----------------
namespace {
constexpr int B = 4, H = 64, W = 64, C = 768;
constexpr int HEADS = 12, HD = 64, WS = 14, HID = 3072;
constexpr int NWIN = 5;               // 70/14
constexpr int NWB  = NWIN * NWIN;     // 25 windows per batch
constexpr int NW   = B * NWB;         // 100 windows
constexpr int L    = WS * WS;         // 196 tokens per window
constexpr int NT   = NW * L;          // 19600 window tokens
constexpr int NP   = B * H * W;       // 16384 real pixels
constexpr int C3   = 3 * C;           // 2304
constexpr int RELN = 2 * WS - 1;      // 27
constexpr float EPS   = 1e-6f;
constexpr float SCALE = 0.125f;       // HD^-0.5
}

// ---------------- scratch (device globals; no allocation allowed) --------
__device__ __half g_ywin_h[(size_t)NT * C];    // LN1 out (window layout, fp16)
__device__ __half g_qkv_h[(size_t)NT * C3];    // qkv (fp16)
__device__ __half g_owin_h[(size_t)NT * C];    // attention out (fp16)
__device__ float  g_x1   [(size_t)NP * C];     // shortcut + proj(o)
__device__ __half g_h2_h [(size_t)NP * C];     // LN2 out (fp16)
__device__ __half g_m1_h [(size_t)NP * HID];   // gelu(fc1) (fp16)
// fp16 TRANSPOSED weights [N, K]
__device__ __half g_qkvw_t[(size_t)C3 * C];
__device__ __half g_projw_t[(size_t)C * C];
__device__ __half g_fc1w_t[(size_t)HID * C];
__device__ __half g_fc2w_t[(size_t)C * HID];

// window-row -> pixel-row index (-1 if padded)
__device__ __forceinline__ int winrow_to_pixel(int t) {
    int nw = t / L, l = t - nw * L;
    int b  = nw / NWB, r = nw - b * NWB;
    int wi = r / NWIN, wj = r - wi * NWIN;
    int i  = l / WS,   j  = l - i * WS;
    int hh = wi * WS + i, ww = wj * WS + j;
    if (hh >= H || ww >= W) return -1;
    return (b * H + hh) * W + ww;
}

__device__ __forceinline__ void mma_f16(float c[4], const uint32_t a[4],
                                        const uint32_t b0, const uint32_t b1) {
    asm volatile(
        "mma.sync.aligned.m16n8k16.row.col.f32.f16.f16.f32 "
        "{%0,%1,%2,%3}, {%4,%5,%6,%7}, {%8,%9}, {%0,%1,%2,%3};"
        : "+f"(c[0]), "+f"(c[1]), "+f"(c[2]), "+f"(c[3])
        : "r"(a[0]), "r"(a[1]), "r"(a[2]), "r"(a[3]), "r"(b0), "r"(b1));
}

__device__ __forceinline__ void ldsm_x4(uint32_t (&r)[4], uint32_t addr) {
    asm volatile(
        "ldmatrix.sync.aligned.m8n8.x4.shared.b16 {%0,%1,%2,%3}, [%4];"
        : "=r"(r[0]), "=r"(r[1]), "=r"(r[2]), "=r"(r[3]) : "r"(addr));
}

__device__ __forceinline__ uint32_t smem_u32(const void* p) {
    uint32_t a;
    asm("{ .reg .u64 t; cvta.to.shared.u64 t, %1; cvt.u32.u64 %0, t; }"
        : "=r"(a) : "l"(p));
    return a;
}

// fast exact-enough gelu: tanh form with HW tanh.approx (MUFU)
__device__ __forceinline__ float fast_gelu(float v) {
    float u = 0.7978845608028654f * (v + 0.044715f * v * v * v);
    float t;
    asm("tanh.approx.f32 %0, %1;" : "=f"(t) : "f"(u));
    return 0.5f * v * (1.f + t);
}

// ---------------- weight transpose fp32 [K,N] -> fp16 [N,K] ----------------
__global__ void wt_kernel(const float* __restrict__ w, __half* __restrict__ wt,
                          int K, int N) {
    __shared__ float s[32][33];
    int n0 = blockIdx.x * 32, k0 = blockIdx.y * 32;
    int tx = threadIdx.x, ty = threadIdx.y;   // 32 x 8
#pragma unroll
    for (int i = 0; i < 32; i += 8)
        s[ty + i][tx] = w[(size_t)(k0 + ty + i) * N + n0 + tx];
    __syncthreads();
#pragma unroll
    for (int i = 0; i < 32; i += 8)
        wt[(size_t)(n0 + ty + i) * K + k0 + tx] = __float2half(s[tx][ty + i]);
}

// ---------------- LN1 + window gather (fp16 out, zero-fill padding) -------
__global__ void ln1_gather_kernel(const float* __restrict__ x,
                                  const float* __restrict__ sc,
                                  const float* __restrict__ bi) {
    int t = blockIdx.x;
    int tid = threadIdx.x;
    __half* y = g_ywin_h + (size_t)t * C;
    int pix = winrow_to_pixel(t);
    if (pix < 0) {
        for (int c = tid; c < C; c += blockDim.x) y[c] = __float2half(0.f);
        return;
    }
    const float* xr = x + (size_t)pix * C;
    float s = 0.f, s2 = 0.f;
    for (int c = tid; c < C; c += blockDim.x) { float v = xr[c]; s += v; s2 += v * v; }
    __shared__ float red[64];
    for (int o = 16; o; o >>= 1) {
        s  += __shfl_xor_sync(0xffffffffu, s, o);
        s2 += __shfl_xor_sync(0xffffffffu, s2, o);
    }
    int warp = tid >> 5, lane = tid & 31;
    if (!lane) { red[warp] = s; red[32 + warp] = s2; }
    __syncthreads();
    if (tid < 32) {
        float a  = (tid < 8) ? red[tid]      : 0.f;
        float b2 = (tid < 8) ? red[32 + tid] : 0.f;
        for (int o = 4; o; o >>= 1) {
            a  += __shfl_xor_sync(0xffffffffu, a, o);
            b2 += __shfl_xor_sync(0xffffffffu, b2, o);
        }
        if (!tid) { red[0] = a; red[1] = b2; }
    }
    __syncthreads();
    float mu  = red[0] / (float)C;
    float var = red[1] / (float)C - mu * mu;
    float inv = rsqrtf(var + EPS);
    for (int c = tid; c < C; c += blockDim.x)
        y[c] = __float2half((xr[c] - mu) * inv * sc[c] + bi[c]);
}

// ---------------- LN over contiguous rows (x1 -> h2 fp16) -----------------
__global__ void ln_rows_kernel(const float* __restrict__ in,
                               const float* __restrict__ sc,
                               const float* __restrict__ bi) {
    int t = blockIdx.x;
    int tid = threadIdx.x;
    const float* xr = in + (size_t)t * C;
    __half* y = g_h2_h + (size_t)t * C;
    float s = 0.f, s2 = 0.f;
    for (int c = tid; c < C; c += blockDim.x) { float v = xr[c]; s += v; s2 += v * v; }
    __shared__ float red[64];
    for (int o = 16; o; o >>= 1) {
        s  += __shfl_xor_sync(0xffffffffu, s, o);
        s2 += __shfl_xor_sync(0xffffffffu, s2, o);
    }
    int warp = tid >> 5, lane = tid & 31;
    if (!lane) { red[warp] = s; red[32 + warp] = s2; }
    __syncthreads();
    if (tid < 32) {
        float a  = (tid < 8) ? red[tid]      : 0.f;
        float b2 = (tid < 8) ? red[32 + tid] : 0.f;
        for (int o = 4; o; o >>= 1) {
            a  += __shfl_xor_sync(0xffffffffu, a, o);
            b2 += __shfl_xor_sync(0xffffffffu, b2, o);
        }
        if (!tid) { red[0] = a; red[1] = b2; }
    }
    __syncthreads();
    float mu  = red[0] / (float)C;
    float var = red[1] / (float)C - mu * mu;
    float inv = rsqrtf(var + EPS);
    for (int c = tid; c < C; c += blockDim.x)
        y[c] = __float2half((xr[c] - mu) * inv * sc[c] + bi[c]);
}

// ---------------- fp16 tensor-core GEMM v8: cp.async BK=64 + ldmatrix ------
// A [M,K] fp16 k-major; Bt [N,K] fp16 k-major (pre-transposed weights).
// 128x128 block tile, 8 warps (4m x 2n), warp tile 32x64, BK=64, 3 stages.
// Fragments via ldmatrix.x4 (row stride 72 halfs: LDSM words 4r mod 32
// distinct -> conflict-free). Mapping verified in R9.
constexpr int HG_RS = 72;                       // halfs per smem row
constexpr int HG_STG = 128 * HG_RS;             // halfs per stage per array
constexpr int HG_SMEM = 3 * HG_STG * 2 * 2;     // bytes (A+B, 3 stages)

template <int MODE>
__global__ void __launch_bounds__(256, 2)
hgemm_kernel(const __half* __restrict__ A,
             const __half* __restrict__ Bt,
             const float* __restrict__ bias,
             const float* __restrict__ aux,
             void* __restrict__ CoutV,
             int M, int N, int K) {
    extern __shared__ __half hsm[];
    __half* Asm = hsm;                 // 3 stages x HG_STG
    __half* Bsm = hsm + 3 * HG_STG;
    float*  Cf = (float*)CoutV;
    __half* Ch = (__half*)CoutV;

    int tid  = threadIdx.x;
    int warp = tid >> 5, lane = tid & 31;
    int wm = warp >> 1, wn = warp & 1;     // 4 x 2 warp grid
    int row0 = blockIdx.y * 128, col0 = blockIdx.x * 128;
    int r = lane >> 2, cq = lane & 3;
    int g = lane >> 3, rowin = lane & 7;

    // staging: srow = tid>>3 (+32i), scp = tid&7 (16B chunk within 64-half row)
    int srow = tid >> 3, scp = tid & 7;
    const __half* AgI[4];
    const __half* BgI[4];
    uint32_t off[4];
    bool aok[4];
#pragma unroll
    for (int i = 0; i < 4; i++) {
        int row = srow + 32 * i;
        aok[i] = (row0 + row) < M;
        AgI[i] = A + (size_t)(row0 + row) * K + scp * 8;
        BgI[i] = Bt + (size_t)(col0 + row) * K + scp * 8;
        off[i] = (uint32_t)(row * HG_RS + scp * 8) * 2;
    }
    uint32_t abase = smem_u32(Asm);
    uint32_t bbase = smem_u32(Bsm);

    // ldmatrix lane offsets (bytes)
    uint32_t a_l = 2u * (uint32_t)(((g & 1) * 8 + rowin) * HG_RS + (g >> 1) * 8);
    uint32_t b_l = 2u * (uint32_t)(((g >> 1) * 8 + rowin) * HG_RS + (g & 1) * 8);

    auto issue = [&](int t) {
        int s = t % 3;
        uint32_t ao = abase + (uint32_t)s * HG_STG * 2;
        uint32_t bo = bbase + (uint32_t)s * HG_STG * 2;
#pragma unroll
        for (int i = 0; i < 4; i++) {
            uint32_t asz = aok[i] ? 16u : 0u;
            asm volatile("cp.async.cg.shared.global [%0], [%1], 16, %2;"
                         :: "r"(ao + off[i]), "l"(AgI[i] + (size_t)t * 64),
                            "r"(asz) : "memory");
            asm volatile("cp.async.cg.shared.global [%0], [%1], 16;"
                         :: "r"(bo + off[i]), "l"(BgI[i] + (size_t)t * 64)
                         : "memory");
        }
    };

    int nk = K >> 6;   // BK=64
    issue(0);
    asm volatile("cp.async.commit_group;" ::: "memory");
    issue(1);
    asm volatile("cp.async.commit_group;" ::: "memory");

    float acc[2][8][4] = {};

    for (int t = 0; t < nk; t++) {
        asm volatile("cp.async.wait_group 1;" ::: "memory");
        __syncthreads();
        if (t + 2 < nk) issue(t + 2);
        asm volatile("cp.async.commit_group;" ::: "memory");   // always

        uint32_t asb = abase + (uint32_t)(t % 3) * HG_STG * 2;
        uint32_t bsb = bbase + (uint32_t)(t % 3) * HG_STG * 2;
#pragma unroll
        for (int ks = 0; ks < 4; ks++) {
            uint32_t k0b = (uint32_t)(ks * 16) * 2;   // byte offset of k0
            uint32_t af[2][4], bq[4][4];
#pragma unroll
            for (int mt = 0; mt < 2; mt++)
                ldsm_x4(af[mt],
                        asb + 2u * (uint32_t)((wm * 32 + mt * 16) * HG_RS) + k0b + a_l);
#pragma unroll
            for (int p = 0; p < 4; p++)
                ldsm_x4(bq[p],
                        bsb + 2u * (uint32_t)((wn * 64 + p * 16) * HG_RS) + k0b + b_l);
#pragma unroll
            for (int nt = 0; nt < 8; nt++) {
                uint32_t b0 = bq[nt >> 1][(nt & 1) * 2];
                uint32_t b1 = bq[nt >> 1][(nt & 1) * 2 + 1];
#pragma unroll
                for (int mt = 0; mt < 2; mt++)
                    mma_f16(acc[mt][nt], af[mt], b0, b1);
            }
        }
    }

    // epilogue: acc[mt][nt][{0,1}] -> row rA cols cb,cb+1 ; [{2,3}] -> rA+8
#pragma unroll
    for (int mt = 0; mt < 2; mt++) {
        int rA = row0 + wm * 32 + mt * 16 + r;
        int rB = rA + 8;
        bool okA = rA < M, okB = rB < M;
        int pixA = -1, pixB = -1;
        if (MODE == 1) {
            if (okA) pixA = winrow_to_pixel(rA);
            if (okB) pixB = winrow_to_pixel(rB);
        }
#pragma unroll
        for (int nt = 0; nt < 8; nt++) {
            int cb = col0 + wn * 64 + nt * 8 + cq * 2;
#pragma unroll
            for (int half = 0; half < 2; half++) {
                int rr = half ? rB : rA;
                bool ok = half ? okB : okA;
                if (!ok) continue;
                float v0 = acc[mt][nt][half * 2 + 0] + bias[cb];
                float v1 = acc[mt][nt][half * 2 + 1] + bias[cb + 1];
                if (MODE == 0) {
                    *(half2*)(Ch + (size_t)rr * N + cb) = __floats2half2_rn(v0, v1);
                } else if (MODE == 1) {
                    int pix = half ? pixB : pixA;
                    if (pix >= 0) {
                        Cf[(size_t)pix * N + cb]     = aux[(size_t)pix * N + cb] + v0;
                        Cf[(size_t)pix * N + cb + 1] = aux[(size_t)pix * N + cb + 1] + v1;
                    }
                } else if (MODE == 2) {
                    *(half2*)(Ch + (size_t)rr * N + cb) =
                        __floats2half2_rn(fast_gelu(v0), fast_gelu(v1));
                } else {
                    Cf[(size_t)rr * N + cb]     = aux[(size_t)rr * N + cb] + v0;
                    Cf[(size_t)rr * N + cb + 1] = aux[(size_t)rr * N + cb + 1] + v1;
                }
            }
        }
    }
}

// ---------------- fused attention v4 (float2-packed probs) -----------------
constexpr int ATTN_SMEM_U32 =
    L * 33 + L * 32 + RELN * 66 + RELN * 66 + 8 * 132 + 8 * 400 + 8 * 64;
constexpr int ATTN_SMEM_BYTES = ATTN_SMEM_U32 * 4;

__global__ void attn_kernel(const float* __restrict__ rph,
                            const float* __restrict__ rpw) {
    extern __shared__ uint32_t smu[];
    half2* Ks2 = (half2*)smu;                  // [l*33 + d2]
    half2* Vs2 = Ks2 + L * 33;                 // [k*32 + lane]
    float* RH = (float*)(Vs2 + L * 32);
    float* RW = RH + RELN * 66;
    float* qb = RW + RELN * 66;
    float* pb = qb + 8 * 132;                  // 8 warps x 200 float2
    float* bb = pb + 8 * 400;

    int wh = blockIdx.x;
    int nw = wh / HEADS, head = wh - nw * HEADS;
    int tid = threadIdx.x;
    size_t base = (size_t)nw * L * C3 + head * HD;

    for (int idx = tid; idx < L * 32; idx += 256) {
        int l = idx >> 5, d2 = idx & 31;
        Ks2[l * 33 + d2] = *(const half2*)&g_qkv_h[base + (size_t)l * C3 + C + 2 * d2];
        Vs2[l * 32 + d2] = *(const half2*)&g_qkv_h[base + (size_t)l * C3 + 2 * C + 2 * d2];
    }
    for (int idx = tid; idx < RELN * HD; idx += 256) {
        int r = idx >> 6, d = idx & 63;
        RH[r * 66 + d] = rph[idx];
        RW[r * 66 + d] = rpw[idx];
    }
    __syncthreads();

    int warp = tid >> 5, lane = tid & 31;
    float* qv0 = qb + warp * 132;
    float* qv1 = qv0 + 66;
    float2* pp = (float2*)(pb + warp * 400);   // 200 float2
    float* bw_ = bb + warp * 64;

    int koff[7];
    int kiL[7], kjL[7];
    bool ok[7];
#pragma unroll
    for (int s = 0; s < 7; s++) {
        int k = lane + 32 * s;
        ok[s] = (k < L);
        int kc = ok[s] ? k : (L - 1);
        kiL[s] = kc / WS;
        kjL[s] = kc - kiL[s] * WS;
        koff[s] = kc * 33;
    }

    for (int p = warp; p < L / 2; p += 8) {
        int q0 = 2 * p, q1 = q0 + 1;
        {
            float2 a = __half22float2(
                *(const half2*)&g_qkv_h[base + (size_t)q0 * C3 + lane * 2]);
            float2 b = __half22float2(
                *(const half2*)&g_qkv_h[base + (size_t)q1 * C3 + lane * 2]);
            *(float2*)&qv0[lane * 2] = a;
            *(float2*)&qv1[lane * 2] = b;
        }
        __syncwarp();

        int qi = q0 / WS, qj0 = q0 - qi * WS, qj1 = qj0 + 1;

        if (lane < 28) {
            int ksub = lane % 14;
            int qsel = lane / 14;
            const float* qp = qsel ? qv1 : qv0;
            const float* hp = RH + (qi - ksub + WS - 1) * 66;
            int qj = qsel ? qj1 : qj0;
            const float* wp = RW + (qj - ksub + WS - 1) * 66;
            float d1 = 0.f, d2a = 0.f;
#pragma unroll 8
            for (int d2 = 0; d2 < 32; d2++) {
                float2 q2 = *(const float2*)&qp[2 * d2];
                float2 h2 = *(const float2*)&hp[2 * d2];
                float2 w2 = *(const float2*)&wp[2 * d2];
                d1  = fmaf(q2.x, h2.x, d1);  d1  = fmaf(q2.y, h2.y, d1);
                d2a = fmaf(q2.x, w2.x, d2a); d2a = fmaf(q2.y, w2.y, d2a);
            }
            bw_[qsel * 14 + ksub] = d1;
            bw_[32 + qsel * 14 + ksub] = d2a;
        }
        __syncwarp();

        float sA[7] = {}, sB[7] = {};
#pragma unroll 8
        for (int d2 = 0; d2 < 32; d2++) {
            float2 qa2 = *(const float2*)&qv0[2 * d2];
            float2 qc2 = *(const float2*)&qv1[2 * d2];
#pragma unroll
            for (int s = 0; s < 7; s++) {
                float2 kf = __half22float2(Ks2[koff[s] + d2]);
                sA[s] = fmaf(qa2.x, kf.x, sA[s]);
                sA[s] = fmaf(qa2.y, kf.y, sA[s]);
                sB[s] = fmaf(qc2.x, kf.x, sB[s]);
                sB[s] = fmaf(qc2.y, kf.y, sB[s]);
            }
        }
        float ltA[7], ltB[7];
#pragma unroll
        for (int s = 0; s < 7; s++) {
            float bhA = bw_[kiL[s]],        bhB = bw_[14 + kiL[s]];
            float bwA = bw_[32 + kjL[s]],   bwB = bw_[46 + kjL[s]];
            ltA[s] = ok[s] ? (sA[s] * SCALE + bhA + bwA) : -1e30f;
            ltB[s] = ok[s] ? (sB[s] * SCALE + bhB + bwB) : -1e30f;
        }

        float mxA = ltA[0], mxB = ltB[0];
#pragma unroll
        for (int s = 1; s < 7; s++) { mxA = fmaxf(mxA, ltA[s]); mxB = fmaxf(mxB, ltB[s]); }
        for (int o = 16; o; o >>= 1) {
            mxA = fmaxf(mxA, __shfl_xor_sync(0xffffffffu, mxA, o));
            mxB = fmaxf(mxB, __shfl_xor_sync(0xffffffffu, mxB, o));
        }
        float smA = 0.f, smB = 0.f;
#pragma unroll
        for (int s = 0; s < 7; s++) {
            ltA[s] = expf(ltA[s] - mxA); smA += ltA[s];
            ltB[s] = expf(ltB[s] - mxB); smB += ltB[s];
        }
        for (int o = 16; o; o >>= 1) {
            smA += __shfl_xor_sync(0xffffffffu, smA, o);
            smB += __shfl_xor_sync(0xffffffffu, smB, o);
        }
        float ivA = 1.f / smA, ivB = 1.f / smB;
#pragma unroll
        for (int s = 0; s < 7; s++) {
            int k = lane + 32 * s;
            if (k < L) pp[k] = make_float2(ltA[s] * ivA, ltB[s] * ivB);
        }
        __syncwarp();

        float a0 = 0.f, a1 = 0.f, b0 = 0.f, b1 = 0.f;
#pragma unroll 4
        for (int k = 0; k < L; k++) {
            float2 vf = __half22float2(Vs2[k * 32 + lane]);
            float2 pr = pp[k];
            a0 = fmaf(pr.x, vf.x, a0);
            a1 = fmaf(pr.x, vf.y, a1);
            b0 = fmaf(pr.y, vf.x, b0);
            b1 = fmaf(pr.y, vf.y, b1);
        }
        size_t orow = ((size_t)nw * L + q0) * C + head * HD + lane * 2;
        *(half2*)&g_owin_h[orow]     = __floats2half2_rn(a0, a1);
        *(half2*)&g_owin_h[orow + C] = __floats2half2_rn(b0, b1);
        __syncwarp();
    }
}

// ---------------- launch ---------------------------------------------------
extern "C" void kernel_launch(void* const* d_in, const int* in_sizes, int n_in,
                              void* d_out, int out_size) {
    const float* x      = (const float*)d_in[0];
    const float* n1s    = (const float*)d_in[1];
    const float* n1b    = (const float*)d_in[2];
    const float* qkvw   = (const float*)d_in[3];
    const float* qkvb   = (const float*)d_in[4];
    const float* rph    = (const float*)d_in[5];
    const float* rpw    = (const float*)d_in[6];
    const float* projw  = (const float*)d_in[7];
    const float* projb  = (const float*)d_in[8];
    const float* n2s    = (const float*)d_in[9];
    const float* n2b    = (const float*)d_in[10];
    const float* fc1w   = (const float*)d_in[11];
    const float* fc1b   = (const float*)d_in[12];
    const float* fc2w   = (const float*)d_in[13];
    const float* fc2b   = (const float*)d_in[14];
    float* out = (float*)d_out;

    cudaFuncSetAttribute(attn_kernel, cudaFuncAttributeMaxDynamicSharedMemorySize,
                         ATTN_SMEM_BYTES);
    cudaFuncSetAttribute(hgemm_kernel<0>, cudaFuncAttributeMaxDynamicSharedMemorySize, HG_SMEM);
    cudaFuncSetAttribute(hgemm_kernel<1>, cudaFuncAttributeMaxDynamicSharedMemorySize, HG_SMEM);
    cudaFuncSetAttribute(hgemm_kernel<2>, cudaFuncAttributeMaxDynamicSharedMemorySize, HG_SMEM);
    cudaFuncSetAttribute(hgemm_kernel<3>, cudaFuncAttributeMaxDynamicSharedMemorySize, HG_SMEM);

    __half* ywin;  cudaGetSymbolAddress((void**)&ywin,  g_ywin_h);
    __half* qkv;   cudaGetSymbolAddress((void**)&qkv,   g_qkv_h);
    __half* owin;  cudaGetSymbolAddress((void**)&owin,  g_owin_h);
    float*  x1;    cudaGetSymbolAddress((void**)&x1,    g_x1);
    __half* h2;    cudaGetSymbolAddress((void**)&h2,    g_h2_h);
    __half* m1;    cudaGetSymbolAddress((void**)&m1,    g_m1_h);
    __half* qkvwt; cudaGetSymbolAddress((void**)&qkvwt, g_qkvw_t);
    __half* projwt;cudaGetSymbolAddress((void**)&projwt,g_projw_t);
    __half* fc1wt; cudaGetSymbolAddress((void**)&fc1wt, g_fc1w_t);
    __half* fc2wt; cudaGetSymbolAddress((void**)&fc2wt, g_fc2w_t);

    // 0) weights -> fp16 transposed [N,K]
    dim3 tb(32, 8);
    wt_kernel<<<dim3(C3 / 32, C / 32), tb>>>(qkvw, qkvwt, C, C3);
    wt_kernel<<<dim3(C / 32, C / 32), tb>>>(projw, projwt, C, C);
    wt_kernel<<<dim3(HID / 32, C / 32), tb>>>(fc1w, fc1wt, C, HID);
    wt_kernel<<<dim3(C / 32, HID / 32), tb>>>(fc2w, fc2wt, HID, C);

    // 1) LN1 + window partition (zero-pad), fp16 out
    ln1_gather_kernel<<<NT, 256>>>(x, n1s, n1b);

    // 2) qkv = ywin @ qkv_w + qkv_b           (19600 x 2304 x 768), fp16 out
    {
        dim3 grid(C3 / 128, (NT + 127) / 128);
        hgemm_kernel<0><<<grid, 256, HG_SMEM>>>(ywin, qkvwt, qkvb, nullptr, qkv, NT, C3, C);
    }

    // 3) fused windowed attention v4, fp16 out
    attn_kernel<<<NW * HEADS, 256, ATTN_SMEM_BYTES>>>(rph, rpw);

    // 4) x1 = shortcut + (owin @ proj_w + proj_b)  (scatter, crop padding)
    {
        dim3 grid(C / 128, (NT + 127) / 128);
        hgemm_kernel<1><<<grid, 256, HG_SMEM>>>(owin, projwt, projb, x, x1, NT, C, C);
    }

    // 5) LN2 -> fp16
    ln_rows_kernel<<<NP, 256>>>(x1, n2s, n2b);

    // 6) m1 = gelu(h2 @ fc1_w + fc1_b)        (16384 x 3072 x 768), fp16 out
    {
        dim3 grid(HID / 128, NP / 128);
        hgemm_kernel<2><<<grid, 256, HG_SMEM>>>(h2, fc1wt, fc1b, nullptr, m1, NP, HID, C);
    }

    // 7) out = x1 + m1 @ fc2_w + fc2_b        (16384 x 768 x 3072), fp32 out
    {
        dim3 grid(C / 128, NP / 128);
        hgemm_kernel<3><<<grid, 256, HG_SMEM>>>(m1, fc2wt, fc2b, x1, out, NP, C, HID);
    }
}